// round 16
// baseline (speedup 1.0000x reference)
#include <cuda_runtime.h>
#include <cstdint>

#define NPL   50000
#define L_TOT 6
#define KN    8
#define FEAT  32
#define H     128
#define MT    32      // nodes per block
#define NT    256     // 8 warps: warp = (16 nodes) x (32 features)
#define SROW  132     // smem row stride (floats)
#define FROW  36
#define EMT   32

#define CH_U2   8192  // uint2 per chunk = 16ks * 16nt * 32 lanes
#define N_CHUNK 21
#define CK_MP0  0
#define CK_MP1  1
#define CK_MPC(i) (2 + 2*(i))
#define CK_NE0  10
#define CK_NE1  12
#define CK_NEC(i) (13 + 2*(i))

__device__ uint2 g_Wf[N_CHUNK * CH_U2];   // tf32 B-fragments

__device__ __forceinline__ float htanh(float x) {
    float y; asm("tanh.approx.f32 %0, %1;" : "=f"(y) : "f"(x)); return y;
}
__device__ __forceinline__ uint32_t f2tf(float x) {
    uint32_t u; asm("cvt.rna.tf32.f32 %0, %1;" : "=r"(u) : "f"(x)); return u;
}
__device__ __forceinline__ void mma_tf32(float c[4], uint32_t a0, uint32_t a1,
                                         uint32_t a2, uint32_t a3,
                                         uint32_t b0, uint32_t b1) {
    asm volatile("mma.sync.aligned.m16n8k8.row.col.f32.tf32.tf32.f32 "
                 "{%0,%1,%2,%3}, {%4,%5,%6,%7}, {%8,%9}, {%0,%1,%2,%3};"
                 : "+f"(c[0]), "+f"(c[1]), "+f"(c[2]), "+f"(c[3])
                 : "r"(a0), "r"(a1), "r"(a2), "r"(a3), "r"(b0), "r"(b1));
}

// Pre-convert all MLP weights into tf32 fragment-native layout (unchanged from R10).
__global__ void pack_wf(const float* __restrict__ Wmp0, const float* __restrict__ Wmp1,
                        const float* __restrict__ Wmpc, const float* __restrict__ Wne0,
                        const float* __restrict__ Wne1, const float* __restrict__ Wnec)
{
    int idx = blockIdx.x * blockDim.x + threadIdx.x;
    if (idx >= N_CHUNK * CH_U2) return;
    int lane = idx & 31;
    int nt   = (idx >> 5) & 15;
    int ks   = (idx >> 9) & 15;
    int c    = idx >> 13;
    int tig = lane & 3, gid = lane >> 2;
    const float* src; int ro;
    if      (c == 0)  { src = Wmp0; ro = 0; }
    else if (c == 1)  { src = Wmp1; ro = 0; }
    else if (c < 10)  { src = Wmpc + ((c - 2) >> 1) * 2*H*H; ro = ((c - 2) & 1) * H; }
    else if (c < 12)  { src = Wne0; ro = (c - 10) * H; }
    else if (c == 12) { src = Wne1; ro = 0; }
    else              { src = Wnec + ((c - 13) >> 1) * 2*H*H; ro = ((c - 13) & 1) * H; }
    int k = 8*ks + tig, n = 8*nt + gid;
    uint2 v;
    v.x = f2tf(src[(ro + k) * H + n]);
    v.y = f2tf(src[(ro + k + 4) * H + n]);
    g_Wf[idx] = v;
}

// One dense-tanh stage: warp computes D[16m x 32n].
__device__ __noinline__ void mstage(const float* __restrict__ SX,
                                    const float* __restrict__ SY,
                                    int chunk, const float* __restrict__ bias,
                                    float* __restrict__ SO,
                                    int m0, int ncol0, int gid, int tig, int lane,
                                    bool cat)
{
    float c[4][4];
#pragma unroll
    for (int nt = 0; nt < 4; nt++) {
        float b0 = __ldg(bias + ncol0 + 8*nt + 2*tig);
        float b1 = __ldg(bias + ncol0 + 8*nt + 2*tig + 1);
        c[nt][0] = b0; c[nt][1] = b1; c[nt][2] = b0; c[nt][3] = b1;
    }
    int nbase = ncol0 >> 3;
    {
        const uint2* Wc = g_Wf + chunk * CH_U2;
        const float* S0 = SX + (m0 + gid) * SROW + tig;
        const float* S1 = SX + (m0 + gid + 8) * SROW + tig;
#pragma unroll 4
        for (int ks = 0; ks < 16; ks++) {
            uint32_t a0 = f2tf(S0[8*ks]);
            uint32_t a1 = f2tf(S1[8*ks]);
            uint32_t a2 = f2tf(S0[8*ks + 4]);
            uint32_t a3 = f2tf(S1[8*ks + 4]);
            const uint2* wrow = Wc + (ks*16 + nbase) * 32 + lane;
#pragma unroll
            for (int nt = 0; nt < 4; nt++) {
                uint2 bb = __ldg(wrow + nt * 32);
                mma_tf32(c[nt], a0, a1, a2, a3, bb.x, bb.y);
            }
        }
    }
    if (cat) {
        const uint2* Wc = g_Wf + (chunk + 1) * CH_U2;
        const float* S0 = SY + (m0 + gid) * SROW + tig;
        const float* S1 = SY + (m0 + gid + 8) * SROW + tig;
#pragma unroll 4
        for (int ks = 0; ks < 16; ks++) {
            uint32_t a0 = f2tf(S0[8*ks]);
            uint32_t a1 = f2tf(S1[8*ks]);
            uint32_t a2 = f2tf(S0[8*ks + 4]);
            uint32_t a3 = f2tf(S1[8*ks + 4]);
            const uint2* wrow = Wc + (ks*16 + nbase) * 32 + lane;
#pragma unroll
            for (int nt = 0; nt < 4; nt++) {
                uint2 bb = __ldg(wrow + nt * 32);
                mma_tf32(c[nt], a0, a1, a2, a3, bb.x, bb.y);
            }
        }
    }
#pragma unroll
    for (int nt = 0; nt < 4; nt++) {
        int col = ncol0 + 8*nt + 2*tig;
        float2 lo = make_float2(htanh(c[nt][0]), htanh(c[nt][1]));
        float2 hi = make_float2(htanh(c[nt][2]), htanh(c[nt][3]));
        *reinterpret_cast<float2*>(SO + (m0 + gid) * SROW + col) = lo;
        *reinterpret_cast<float2*>(SO + (m0 + gid + 8) * SROW + col) = hi;
    }
}

// base = tanh(nf @ W_embed + b_embed) -> emb (= d_out)
__global__ void __launch_bounds__(128)
embed_kernel(const float* __restrict__ nf, const float* __restrict__ W,
             const float* __restrict__ b, float* __restrict__ out, int n_nodes)
{
    __shared__ float S[EMT * FROW];
    int t    = threadIdx.x;
    int f    = t;
    int base = blockIdx.x * EMT;

    for (int i = t; i < EMT * FEAT; i += 128) {
        int m = i / FEAT, k = i % FEAT;
        int row = base + m;
        if (row >= n_nodes) row = n_nodes - 1;
        S[m * FROW + k] = nf[(long)row * FEAT + k];
    }
    __syncthreads();

    float acc[EMT];
    float bias = __ldg(b + f);
#pragma unroll
    for (int m = 0; m < EMT; m++) acc[m] = bias;

#pragma unroll 2
    for (int k = 0; k < FEAT; k += 4) {
        float w0 = __ldg(W + (k+0)*H + f);
        float w1 = __ldg(W + (k+1)*H + f);
        float w2 = __ldg(W + (k+2)*H + f);
        float w3 = __ldg(W + (k+3)*H + f);
#pragma unroll
        for (int m = 0; m < EMT; m++) {
            float4 a = *reinterpret_cast<const float4*>(S + m*FROW + k);
            acc[m] = fmaf(a.x, w0, acc[m]);
            acc[m] = fmaf(a.y, w1, acc[m]);
            acc[m] = fmaf(a.z, w2, acc[m]);
            acc[m] = fmaf(a.w, w3, acc[m]);
        }
    }
#pragma unroll
    for (int m = 0; m < EMT; m++) {
        int row = base + m;
        if (row < n_nodes) out[(long)row * H + f] = htanh(acc[m]);
    }
}

// Full GNN layer on tensor pipe, 8 warps per block.
__global__ void __launch_bounds__(NT)
layer_kernel(float* emb, const int* __restrict__ src, int lyr,
             const float* __restrict__ bmp0, const float* __restrict__ bmp1,
             const float* __restrict__ bmpc,
             const float* __restrict__ bne0, const float* __restrict__ bne1,
             const float* __restrict__ bnec)
{
    extern __shared__ float smem[];
    float* A = smem;                   // [MT][SROW]
    float* B = A + MT * SROW;
    float* C = B + MT * SROW;
    int*   sidx = (int*)(C + MT * SROW);

    int t    = threadIdx.x;
    int lane = t & 31;
    int w    = t >> 5;
    int gid  = lane >> 2;
    int tig  = lane & 3;
    int m0    = (w & 1) * 16;    // warp's node-tile
    int ncol0 = (w >> 1) * 32;   // warp's feature-tile (32 cols)
    int d0   = blockIdx.x * MT;

    const int* __restrict__ srcL = src + (long)(lyr - 1) * NPL * KN;
    if (t < MT * KN) {
        int node = d0 + t / KN;
        if (node >= NPL) node = NPL - 1;
        sidx[t] = srcL[(long)node * KN + (t % KN)];
    }
    __syncthreads();

    // gather: A[m][f] = sum of 8 neighbor rows; f = t&127, half = t>>7
    {
        int f = t & 127;
        int half = t >> 7;
#pragma unroll 2
        for (int m = half; m < MT; m += 2) {
            float s = 0.f;
#pragma unroll
            for (int k = 0; k < KN; k++) {
                int row = sidx[m * KN + k];
                s += __ldg(emb + (long)row * H + f);
            }
            A[m * SROW + f] = s;
        }
    }
    __syncthreads();

    // message-passing MLP
    mstage(A, nullptr, CK_MP0, bmp0, B, m0, ncol0, gid, tig, lane, false); __syncthreads();
    mstage(B, nullptr, CK_MP1, bmp1, C, m0, ncol0, gid, tig, lane, false); __syncthreads();
    mstage(C, B, CK_MPC(0), bmpc + 0*H, A, m0, ncol0, gid, tig, lane, true); __syncthreads();
    mstage(A, B, CK_MPC(1), bmpc + 1*H, C, m0, ncol0, gid, tig, lane, true); __syncthreads();
    mstage(C, B, CK_MPC(2), bmpc + 2*H, A, m0, ncol0, gid, tig, lane, true); __syncthreads();
    mstage(A, B, CK_MPC(3), bmpc + 3*H, C, m0, ncol0, gid, tig, lane, true); __syncthreads(); // r->C

    // this layer's base embedding -> A
    {
        int f = t & 127;
        int half = t >> 7;
#pragma unroll 2
        for (int m = half; m < MT; m += 2) {
            int node = d0 + m;
            if (node >= NPL) node = NPL - 1;
            A[m * SROW + f] = __ldg(emb + (long)(lyr * NPL + node) * H + f);
        }
    }
    __syncthreads();

    // node-embedding MLP
    mstage(A, C, CK_NE0, bne0, B, m0, ncol0, gid, tig, lane, true); __syncthreads();
    mstage(B, nullptr, CK_NE1, bne1, A, m0, ncol0, gid, tig, lane, false); __syncthreads();
    mstage(A, B, CK_NEC(0), bnec + 0*H, C, m0, ncol0, gid, tig, lane, true); __syncthreads();
    mstage(C, B, CK_NEC(1), bnec + 1*H, A, m0, ncol0, gid, tig, lane, true); __syncthreads();
    mstage(A, B, CK_NEC(2), bnec + 2*H, C, m0, ncol0, gid, tig, lane, true); __syncthreads();
    mstage(C, B, CK_NEC(3), bnec + 3*H, A, m0, ncol0, gid, tig, lane, true); __syncthreads(); // e->A

    {
        int f = t & 127;
        int half = t >> 7;
#pragma unroll 2
        for (int m = half; m < MT; m += 2) {
            int node = d0 + m;
            if (node < NPL)
                emb[(long)(lyr * NPL + node) * H + f] = A[m * SROW + f];
        }
    }
}

extern "C" void kernel_launch(void* const* d_in, const int* in_sizes, int n_in,
                              void* d_out, int out_size)
{
    const float* nf      = (const float*)d_in[0];
    const int*   src     = (const int*)  d_in[1];
    const float* W_embed = (const float*)d_in[3];
    const float* b_embed = (const float*)d_in[4];
    const float* W_mp0   = (const float*)d_in[5];
    const float* b_mp0   = (const float*)d_in[6];
    const float* W_mp1   = (const float*)d_in[7];
    const float* b_mp1   = (const float*)d_in[8];
    const float* W_mpc   = (const float*)d_in[9];
    const float* b_mpc   = (const float*)d_in[10];
    const float* W_ne0   = (const float*)d_in[11];
    const float* b_ne0   = (const float*)d_in[12];
    const float* W_ne1   = (const float*)d_in[13];
    const float* b_ne1   = (const float*)d_in[14];
    const float* W_nec   = (const float*)d_in[15];
    const float* b_nec   = (const float*)d_in[16];

    float* out = (float*)d_out;

    const int smem_bytes = 3 * MT * SROW * (int)sizeof(float) + MT * KN * (int)sizeof(int);
    cudaFuncSetAttribute(layer_kernel, cudaFuncAttributeMaxDynamicSharedMemorySize, smem_bytes);

    pack_wf<<<(N_CHUNK * CH_U2 + 255) / 256, 256>>>(W_mp0, W_mp1, W_mpc, W_ne0, W_ne1, W_nec);

    const int n_nodes = L_TOT * NPL;
    embed_kernel<<<(n_nodes + EMT - 1) / EMT, 128>>>(nf, W_embed, b_embed, out, n_nodes);

    const int layer_blocks = (NPL + MT - 1) / MT;
    for (int l = 1; l < L_TOT; l++) {
        layer_kernel<<<layer_blocks, NT, smem_bytes>>>(out, src, l,
                                           b_mp0, b_mp1, b_mpc, b_ne0, b_ne1, b_nec);
    }
}

// round 17
// speedup vs baseline: 1.0240x; 1.0240x over previous
#include <cuda_runtime.h>
#include <cstdint>

#define NPL   50000
#define L_TOT 6
#define KN    8
#define FEAT  32
#define H     128
#define MT    32      // nodes per block
#define NT    256     // 8 warps: warp = (16 nodes) x (32 features)
#define SROW  136     // smem row stride (floats): 8 mod 32 -> conflict-free frag LDS.64
#define FROW  36
#define EMT   32

#define CH_U4   4096  // uint4 per chunk = 16ks * 8np * 32 lanes
#define N_CHUNK 21
#define CK_MP0  0
#define CK_MP1  1
#define CK_MPC(i) (2 + 2*(i))
#define CK_NE0  10
#define CK_NE1  12
#define CK_NEC(i) (13 + 2*(i))

__device__ uint4 g_Wf[N_CHUNK * CH_U4];   // tf32 B-fragments, 2 ntiles per uint4

__device__ __forceinline__ float htanh(float x) {
    float y; asm("tanh.approx.f32 %0, %1;" : "=f"(y) : "f"(x)); return y;
}
__device__ __forceinline__ uint32_t f2tf(float x) {
    uint32_t u; asm("cvt.rna.tf32.f32 %0, %1;" : "=r"(u) : "f"(x)); return u;
}
__device__ __forceinline__ void mma_tf32(float c[4], uint32_t a0, uint32_t a1,
                                         uint32_t a2, uint32_t a3,
                                         uint32_t b0, uint32_t b1) {
    asm volatile("mma.sync.aligned.m16n8k8.row.col.f32.tf32.tf32.f32 "
                 "{%0,%1,%2,%3}, {%4,%5,%6,%7}, {%8,%9}, {%0,%1,%2,%3};"
                 : "+f"(c[0]), "+f"(c[1]), "+f"(c[2]), "+f"(c[3])
                 : "r"(a0), "r"(a1), "r"(a2), "r"(a3), "r"(b0), "r"(b1));
}

// feature-axis permutation within each 8-group: r -> 2*(r&3) + (r>>2)
// makes each thread's (k, k+4) A-frag pair adjacent in smem.
__device__ __forceinline__ int permf(int f) {
    int r = f & 7;
    return (f & ~7) | (2 * (r & 3)) | (r >> 2);
}

// Pre-convert all MLP weights into tf32 fragment-native layout, 2 ntiles per uint4.
// [chunk][(ks*8+np)*32+lane] = {b0(nt=2np), b1(2np), b0(2np+1), b1(2np+1)}
__global__ void pack_wf(const float* __restrict__ Wmp0, const float* __restrict__ Wmp1,
                        const float* __restrict__ Wmpc, const float* __restrict__ Wne0,
                        const float* __restrict__ Wne1, const float* __restrict__ Wnec)
{
    int idx = blockIdx.x * blockDim.x + threadIdx.x;
    if (idx >= N_CHUNK * CH_U4) return;
    int lane = idx & 31;
    int np   = (idx >> 5) & 7;
    int ks   = (idx >> 8) & 15;
    int c    = idx >> 12;
    int tig = lane & 3, gid = lane >> 2;
    const float* src; int ro;
    if      (c == 0)  { src = Wmp0; ro = 0; }
    else if (c == 1)  { src = Wmp1; ro = 0; }
    else if (c < 10)  { src = Wmpc + ((c - 2) >> 1) * 2*H*H; ro = ((c - 2) & 1) * H; }
    else if (c < 12)  { src = Wne0; ro = (c - 10) * H; }
    else if (c == 12) { src = Wne1; ro = 0; }
    else              { src = Wnec + ((c - 13) >> 1) * 2*H*H; ro = ((c - 13) & 1) * H; }
    int k  = 8*ks + tig;
    int n0 = 16*np + gid;          // nt = 2np
    int n1 = 16*np + 8 + gid;      // nt = 2np+1
    uint4 v;
    v.x = f2tf(src[(ro + k    ) * H + n0]);
    v.y = f2tf(src[(ro + k + 4) * H + n0]);
    v.z = f2tf(src[(ro + k    ) * H + n1]);
    v.w = f2tf(src[(ro + k + 4) * H + n1]);
    g_Wf[idx] = v;
}

// One dense-tanh stage: warp computes D[16m x 32n]. smem activations are perm-laid.
__device__ __noinline__ void mstage(const float* __restrict__ SX,
                                    const float* __restrict__ SY,
                                    int chunk, const float* __restrict__ bias,
                                    float* __restrict__ SO,
                                    int m0, int ncol0, int gid, int tig, int lane,
                                    bool cat)
{
    float c[4][4];
#pragma unroll
    for (int nt = 0; nt < 4; nt++) {
        float b0 = __ldg(bias + ncol0 + 8*nt + 2*tig);
        float b1 = __ldg(bias + ncol0 + 8*nt + 2*tig + 1);
        c[nt][0] = b0; c[nt][1] = b1; c[nt][2] = b0; c[nt][3] = b1;
    }
    int npbase = ncol0 >> 4;   // first npair within chunk
    {
        const uint4* Wc = g_Wf + chunk * CH_U4;
        const float* S0 = SX + (m0 + gid) * SROW + 2*tig;
        const float* S1 = SX + (m0 + gid + 8) * SROW + 2*tig;
        const uint4* wrow = Wc + npbase * 32 + lane;
#pragma unroll 4
        for (int ks = 0; ks < 16; ks++) {
            float2 aA = *reinterpret_cast<const float2*>(S0 + 8*ks);  // (a0, a2)
            float2 aB = *reinterpret_cast<const float2*>(S1 + 8*ks);  // (a1, a3)
            uint32_t a0 = f2tf(aA.x), a2 = f2tf(aA.y);
            uint32_t a1 = f2tf(aB.x), a3 = f2tf(aB.y);
            uint4 w0 = __ldg(wrow + ks*8*32);
            uint4 w1 = __ldg(wrow + ks*8*32 + 32);
            mma_tf32(c[0], a0, a1, a2, a3, w0.x, w0.y);
            mma_tf32(c[1], a0, a1, a2, a3, w0.z, w0.w);
            mma_tf32(c[2], a0, a1, a2, a3, w1.x, w1.y);
            mma_tf32(c[3], a0, a1, a2, a3, w1.z, w1.w);
        }
    }
    if (cat) {
        const uint4* Wc = g_Wf + (chunk + 1) * CH_U4;
        const float* S0 = SY + (m0 + gid) * SROW + 2*tig;
        const float* S1 = SY + (m0 + gid + 8) * SROW + 2*tig;
        const uint4* wrow = Wc + npbase * 32 + lane;
#pragma unroll 4
        for (int ks = 0; ks < 16; ks++) {
            float2 aA = *reinterpret_cast<const float2*>(S0 + 8*ks);
            float2 aB = *reinterpret_cast<const float2*>(S1 + 8*ks);
            uint32_t a0 = f2tf(aA.x), a2 = f2tf(aA.y);
            uint32_t a1 = f2tf(aB.x), a3 = f2tf(aB.y);
            uint4 w0 = __ldg(wrow + ks*8*32);
            uint4 w1 = __ldg(wrow + ks*8*32 + 32);
            mma_tf32(c[0], a0, a1, a2, a3, w0.x, w0.y);
            mma_tf32(c[1], a0, a1, a2, a3, w0.z, w0.w);
            mma_tf32(c[2], a0, a1, a2, a3, w1.x, w1.y);
            mma_tf32(c[3], a0, a1, a2, a3, w1.z, w1.w);
        }
    }
    // epilogue: permuted scalar stores. feature r=2tig -> pos 2*(2tig&3)+(tig>>1)... compute directly
    int r0 = 2*tig, r1 = 2*tig + 1;
    int p0 = 2*(r0 & 3) + (r0 >> 2);
    int p1 = 2*(r1 & 3) + (r1 >> 2);
#pragma unroll
    for (int nt = 0; nt < 4; nt++) {
        float* baseLo = SO + (m0 + gid) * SROW + ncol0 + 8*nt;
        float* baseHi = SO + (m0 + gid + 8) * SROW + ncol0 + 8*nt;
        baseLo[p0] = htanh(c[nt][0]);
        baseLo[p1] = htanh(c[nt][1]);
        baseHi[p0] = htanh(c[nt][2]);
        baseHi[p1] = htanh(c[nt][3]);
    }
}

// base = tanh(nf @ W_embed + b_embed) -> emb (= d_out)
__global__ void __launch_bounds__(128)
embed_kernel(const float* __restrict__ nf, const float* __restrict__ W,
             const float* __restrict__ b, float* __restrict__ out, int n_nodes)
{
    __shared__ float S[EMT * FROW];
    int t    = threadIdx.x;
    int f    = t;
    int base = blockIdx.x * EMT;

    for (int i = t; i < EMT * FEAT; i += 128) {
        int m = i / FEAT, k = i % FEAT;
        int row = base + m;
        if (row >= n_nodes) row = n_nodes - 1;
        S[m * FROW + k] = nf[(long)row * FEAT + k];
    }
    __syncthreads();

    float acc[EMT];
    float bias = __ldg(b + f);
#pragma unroll
    for (int m = 0; m < EMT; m++) acc[m] = bias;

#pragma unroll 2
    for (int k = 0; k < FEAT; k += 4) {
        float w0 = __ldg(W + (k+0)*H + f);
        float w1 = __ldg(W + (k+1)*H + f);
        float w2 = __ldg(W + (k+2)*H + f);
        float w3 = __ldg(W + (k+3)*H + f);
#pragma unroll
        for (int m = 0; m < EMT; m++) {
            float4 a = *reinterpret_cast<const float4*>(S + m*FROW + k);
            acc[m] = fmaf(a.x, w0, acc[m]);
            acc[m] = fmaf(a.y, w1, acc[m]);
            acc[m] = fmaf(a.z, w2, acc[m]);
            acc[m] = fmaf(a.w, w3, acc[m]);
        }
    }
#pragma unroll
    for (int m = 0; m < EMT; m++) {
        int row = base + m;
        if (row < n_nodes) out[(long)row * H + f] = htanh(acc[m]);
    }
}

// Full GNN layer on tensor pipe, 8 warps per block, permuted activation smem.
__global__ void __launch_bounds__(NT)
layer_kernel(float* emb, const int* __restrict__ src, int lyr,
             const float* __restrict__ bmp0, const float* __restrict__ bmp1,
             const float* __restrict__ bmpc,
             const float* __restrict__ bne0, const float* __restrict__ bne1,
             const float* __restrict__ bnec)
{
    extern __shared__ float smem[];
    float* A = smem;                   // [MT][SROW], features permuted by permf
    float* B = A + MT * SROW;
    float* C = B + MT * SROW;
    int*   sidx = (int*)(C + MT * SROW);

    int t    = threadIdx.x;
    int lane = t & 31;
    int w    = t >> 5;
    int gid  = lane >> 2;
    int tig  = lane & 3;
    int m0    = (w & 1) * 16;
    int ncol0 = (w >> 1) * 32;
    int d0   = blockIdx.x * MT;

    const int* __restrict__ srcL = src + (long)(lyr - 1) * NPL * KN;
    if (t < MT * KN) {
        int node = d0 + t / KN;
        if (node >= NPL) node = NPL - 1;
        sidx[t] = srcL[(long)node * KN + (t % KN)];
    }
    __syncthreads();

    // gather: A[m][permf(f)] = sum of 8 neighbor rows
    {
        int f  = t & 127;
        int pf = permf(f);
        int half = t >> 7;
#pragma unroll 2
        for (int m = half; m < MT; m += 2) {
            float s = 0.f;
#pragma unroll
            for (int k = 0; k < KN; k++) {
                int row = sidx[m * KN + k];
                s += __ldg(emb + (long)row * H + f);
            }
            A[m * SROW + pf] = s;
        }
    }
    __syncthreads();

    // message-passing MLP
    mstage(A, nullptr, CK_MP0, bmp0, B, m0, ncol0, gid, tig, lane, false); __syncthreads();
    mstage(B, nullptr, CK_MP1, bmp1, C, m0, ncol0, gid, tig, lane, false); __syncthreads();
    mstage(C, B, CK_MPC(0), bmpc + 0*H, A, m0, ncol0, gid, tig, lane, true); __syncthreads();
    mstage(A, B, CK_MPC(1), bmpc + 1*H, C, m0, ncol0, gid, tig, lane, true); __syncthreads();
    mstage(C, B, CK_MPC(2), bmpc + 2*H, A, m0, ncol0, gid, tig, lane, true); __syncthreads();
    mstage(A, B, CK_MPC(3), bmpc + 3*H, C, m0, ncol0, gid, tig, lane, true); __syncthreads(); // r->C

    // this layer's base embedding -> A (permuted)
    {
        int f  = t & 127;
        int pf = permf(f);
        int half = t >> 7;
#pragma unroll 2
        for (int m = half; m < MT; m += 2) {
            int node = d0 + m;
            if (node >= NPL) node = NPL - 1;
            A[m * SROW + pf] = __ldg(emb + (long)(lyr * NPL + node) * H + f);
        }
    }
    __syncthreads();

    // node-embedding MLP
    mstage(A, C, CK_NE0, bne0, B, m0, ncol0, gid, tig, lane, true); __syncthreads();
    mstage(B, nullptr, CK_NE1, bne1, A, m0, ncol0, gid, tig, lane, false); __syncthreads();
    mstage(A, B, CK_NEC(0), bnec + 0*H, C, m0, ncol0, gid, tig, lane, true); __syncthreads();
    mstage(C, B, CK_NEC(1), bnec + 1*H, A, m0, ncol0, gid, tig, lane, true); __syncthreads();
    mstage(A, B, CK_NEC(2), bnec + 2*H, C, m0, ncol0, gid, tig, lane, true); __syncthreads();
    mstage(C, B, CK_NEC(3), bnec + 3*H, A, m0, ncol0, gid, tig, lane, true); __syncthreads(); // e->A

    {
        int f  = t & 127;
        int pf = permf(f);
        int half = t >> 7;
#pragma unroll 2
        for (int m = half; m < MT; m += 2) {
            int node = d0 + m;
            if (node < NPL)
                emb[(long)(lyr * NPL + node) * H + f] = A[m * SROW + pf];
        }
    }
}

extern "C" void kernel_launch(void* const* d_in, const int* in_sizes, int n_in,
                              void* d_out, int out_size)
{
    const float* nf      = (const float*)d_in[0];
    const int*   src     = (const int*)  d_in[1];
    const float* W_embed = (const float*)d_in[3];
    const float* b_embed = (const float*)d_in[4];
    const float* W_mp0   = (const float*)d_in[5];
    const float* b_mp0   = (const float*)d_in[6];
    const float* W_mp1   = (const float*)d_in[7];
    const float* b_mp1   = (const float*)d_in[8];
    const float* W_mpc   = (const float*)d_in[9];
    const float* b_mpc   = (const float*)d_in[10];
    const float* W_ne0   = (const float*)d_in[11];
    const float* b_ne0   = (const float*)d_in[12];
    const float* W_ne1   = (const float*)d_in[13];
    const float* b_ne1   = (const float*)d_in[14];
    const float* W_nec   = (const float*)d_in[15];
    const float* b_nec   = (const float*)d_in[16];

    float* out = (float*)d_out;

    const int smem_bytes = 3 * MT * SROW * (int)sizeof(float) + MT * KN * (int)sizeof(int);
    cudaFuncSetAttribute(layer_kernel, cudaFuncAttributeMaxDynamicSharedMemorySize, smem_bytes);

    pack_wf<<<(N_CHUNK * CH_U4 + 255) / 256, 256>>>(W_mp0, W_mp1, W_mpc, W_ne0, W_ne1, W_nec);

    const int n_nodes = L_TOT * NPL;
    embed_kernel<<<(n_nodes + EMT - 1) / EMT, 128>>>(nf, W_embed, b_embed, out, n_nodes);

    const int layer_blocks = (NPL + MT - 1) / MT;
    for (int l = 1; l < L_TOT; l++) {
        layer_kernel<<<layer_blocks, NT, smem_bytes>>>(out, src, l,
                                           b_mp0, b_mp1, b_mpc, b_ne0, b_ne1, b_nec);
    }
}